// round 8
// baseline (speedup 1.0000x reference)
#include <cuda_runtime.h>
#include <cstdint>

// Problem: input (512, 2048, 7, 7) fp32 -> per row of 49: mean of top-4.
// Output: (512, 2048, 1, 1) = 1,048,576 floats.
//
// R7: R5 pipeline (persistent, double-buffered cp.async.bulk, 296 blocks,
// 256 thr, 1 row/thread) + TREE-shaped top-4 reduction: 6 independent
// (sort4,sort4,merge) subtrees, then 6->3->2->1 merges. Same op count as the
// linear merge but critical path 12 merges -> 4 levels, 6-way ILP per thread.

#define THREADS      256
#define TILE_ROWS    256
#define ROW_LEN      49
#define TILE_FLOATS  (TILE_ROWS * ROW_LEN)   // 12544
#define TILE_BYTES   (TILE_FLOATS * 4)       // 50176
#define GRID_BLOCKS  296                     // 2 CTAs x 148 SMs exactly

struct S4 { float a, b, c, d; };

__device__ __forceinline__ void ce(float& x, float& y) {
    float hi = fmaxf(x, y);
    float lo = fminf(x, y);
    x = hi; y = lo;
}

__device__ __forceinline__ S4 sort4(float a, float b, float c, float d) {
    ce(a, b); ce(c, d); ce(a, c); ce(b, d); ce(b, c);
    return {a, b, c, d};
}

// top-4 of two sorted-desc quads (bitonic split + 4-CE resort)
__device__ __forceinline__ S4 merge4(S4 t, S4 q) {
    float m0 = fmaxf(t.a, q.d);
    float m1 = fmaxf(t.b, q.c);
    float m2 = fmaxf(t.c, q.b);
    float m3 = fmaxf(t.d, q.a);
    ce(m0, m2); ce(m1, m3); ce(m0, m1); ce(m2, m3);
    return {m0, m1, m2, m3};
}

__device__ __forceinline__ void mbar_init(uint32_t a, uint32_t cnt) {
    asm volatile("mbarrier.init.shared.b64 [%0], %1;" :: "r"(a), "r"(cnt) : "memory");
}

__device__ __forceinline__ void mbar_expect_tx(uint32_t a, uint32_t bytes) {
    asm volatile("mbarrier.arrive.expect_tx.shared.b64 _, [%0], %1;"
                 :: "r"(a), "r"(bytes) : "memory");
}

__device__ __forceinline__ void mbar_wait(uint32_t a, uint32_t parity) {
    asm volatile(
        "{\n\t"
        ".reg .pred p;\n\t"
        "WAIT_%=:\n\t"
        "mbarrier.try_wait.parity.shared.b64 p, [%0], %1;\n\t"
        "@!p bra WAIT_%=;\n\t"
        "}"
        :: "r"(a), "r"(parity) : "memory");
}

__device__ __forceinline__ void bulk_copy(uint32_t smem_dst, const void* gmem_src,
                                          uint32_t bytes, uint32_t mbar) {
    asm volatile(
        "cp.async.bulk.shared::cta.global.mbarrier::complete_tx::bytes "
        "[%0], [%1], %2, [%3];"
        :: "r"(smem_dst), "l"(gmem_src), "r"(bytes), "r"(mbar) : "memory");
}

__global__ __launch_bounds__(THREADS)
void apool_topk4_kernel(const float* __restrict__ in, float* __restrict__ out,
                        int ntiles) {
    extern __shared__ float s[];                 // 2 * TILE_FLOATS
    __shared__ __align__(8) uint64_t mbar_s[2];

    const int tid = threadIdx.x;
    const uint32_t s_base = (uint32_t)__cvta_generic_to_shared(s);
    const uint32_t mb[2] = { (uint32_t)__cvta_generic_to_shared(&mbar_s[0]),
                             (uint32_t)__cvta_generic_to_shared(&mbar_s[1]) };

    if (tid == 0) {
        mbar_init(mb[0], 1);
        mbar_init(mb[1], 1);
        asm volatile("fence.proxy.async.shared::cta;" ::: "memory");
    }
    __syncthreads();

    // ---- Prologue: issue first tile into buffer 0 ----
    int t = blockIdx.x;
    if (t < ntiles && tid == 0) {
        mbar_expect_tx(mb[0], TILE_BYTES);
        bulk_copy(s_base, in + (long long)t * TILE_FLOATS, TILE_BYTES, mb[0]);
    }

    int it = 0;
    for (; t < ntiles; t += GRID_BLOCKS, it++) {
        const int buf = it & 1;
        const uint32_t par = (uint32_t)(it >> 1) & 1u;

        // issue next tile into the other buffer (prev-iter __syncthreads
        // guarantees that buffer is no longer being read)
        const int tn = t + GRID_BLOCKS;
        if (tn < ntiles && tid == 0) {
            const int nb = buf ^ 1;
            mbar_expect_tx(mb[nb], TILE_BYTES);
            bulk_copy(s_base + (uint32_t)nb * (uint32_t)TILE_BYTES,
                      in + (long long)tn * TILE_FLOATS, TILE_BYTES, mb[nb]);
        }

        // wait for current tile's DMA completion
        mbar_wait(mb[buf], par);

        // ---- Compute: one row per thread, tree reduction ----
        const float* row = s + buf * TILE_FLOATS + tid * ROW_LEN;

        // 6 independent subtrees over chunk pairs (elems 0..47)
        S4 m[6];
        #pragma unroll
        for (int k = 0; k < 6; k++) {
            const float* p = row + 8 * k;
            S4 x = sort4(p[0], p[1], p[2], p[3]);
            S4 y = sort4(p[4], p[5], p[6], p[7]);
            m[k] = merge4(x, y);
        }
        // 6 -> 3
        S4 n0 = merge4(m[0], m[1]);
        S4 n1 = merge4(m[2], m[3]);
        S4 n2 = merge4(m[4], m[5]);
        // 3 -> 1
        S4 p0 = merge4(n0, n1);
        S4 q  = merge4(p0, n2);

        // insert element 48
        float e = row[48];
        q.d = fmaxf(q.d, e);
        ce(q.c, q.d); ce(q.b, q.c); ce(q.a, q.b);

        out[(long long)t * TILE_ROWS + tid] = (q.a + q.b + q.c + q.d) * 0.25f;

        __syncthreads();   // all done reading buf before it gets overwritten
    }
}

extern "C" void kernel_launch(void* const* d_in, const int* in_sizes, int n_in,
                              void* d_out, int out_size) {
    const float* in = (const float*)d_in[0];
    float* out = (float*)d_out;

    const int rows = out_size;                 // 1,048,576
    const int ntiles = rows / TILE_ROWS;       // 4096, divides exactly
    const int smem = 2 * TILE_BYTES;           // 100,352 B

    cudaFuncSetAttribute(apool_topk4_kernel,
                         cudaFuncAttributeMaxDynamicSharedMemorySize, smem);
    apool_topk4_kernel<<<GRID_BLOCKS, THREADS, smem>>>(in, out, ntiles);
}

// round 9
// speedup vs baseline: 1.0607x; 1.0607x over previous
#include <cuda_runtime.h>
#include <cstdint>

// Problem: input (512, 2048, 7, 7) fp32 -> per row of 49: mean of top-4.
// Output: (512, 2048, 1, 1) = 1,048,576 floats.
//
// R8: one tile per CTA, pipelining via the CTA scheduler instead of an
// in-kernel ring. 4096 blocks x 256 threads; each block: one cp.async.bulk
// of its 50,176B tile -> mbarrier wait -> one row per thread (R2 linear
// sort4+bitonic-merge) -> store -> exit. Single 50KB smem buffer -> 4 CTAs
// resident per SM (32 warps, occ ~50%), 4 concurrent DMA streams per SM;
// newly-scheduled CTAs' copies overlap resident CTAs' compute.

#define THREADS      256
#define TILE_ROWS    256
#define ROW_LEN      49
#define TILE_FLOATS  (TILE_ROWS * ROW_LEN)   // 12544
#define TILE_BYTES   (TILE_FLOATS * 4)       // 50176

__device__ __forceinline__ void ce(float& x, float& y) {
    float hi = fmaxf(x, y);
    float lo = fminf(x, y);
    x = hi; y = lo;
}

__device__ __forceinline__ void sort4(float& a, float& b, float& c, float& d) {
    ce(a, b); ce(c, d); ce(a, c); ce(b, d); ce(b, c);
}

__device__ __forceinline__ void merge4(float& t0, float& t1, float& t2, float& t3,
                                       float c0, float c1, float c2, float c3) {
    float m0 = fmaxf(t0, c3);
    float m1 = fmaxf(t1, c2);
    float m2 = fmaxf(t2, c1);
    float m3 = fmaxf(t3, c0);
    ce(m0, m2); ce(m1, m3); ce(m0, m1); ce(m2, m3);
    t0 = m0; t1 = m1; t2 = m2; t3 = m3;
}

__device__ __forceinline__ void mbar_init(uint32_t a, uint32_t cnt) {
    asm volatile("mbarrier.init.shared.b64 [%0], %1;" :: "r"(a), "r"(cnt) : "memory");
}

__device__ __forceinline__ void mbar_expect_tx(uint32_t a, uint32_t bytes) {
    asm volatile("mbarrier.arrive.expect_tx.shared.b64 _, [%0], %1;"
                 :: "r"(a), "r"(bytes) : "memory");
}

__device__ __forceinline__ void mbar_wait(uint32_t a, uint32_t parity) {
    asm volatile(
        "{\n\t"
        ".reg .pred p;\n\t"
        "WAIT_%=:\n\t"
        "mbarrier.try_wait.parity.shared.b64 p, [%0], %1;\n\t"
        "@!p bra WAIT_%=;\n\t"
        "}"
        :: "r"(a), "r"(parity) : "memory");
}

__device__ __forceinline__ void bulk_copy(uint32_t smem_dst, const void* gmem_src,
                                          uint32_t bytes, uint32_t mbar) {
    asm volatile(
        "cp.async.bulk.shared::cta.global.mbarrier::complete_tx::bytes "
        "[%0], [%1], %2, [%3];"
        :: "r"(smem_dst), "l"(gmem_src), "r"(bytes), "r"(mbar) : "memory");
}

__global__ __launch_bounds__(THREADS)
void apool_topk4_kernel(const float* __restrict__ in, float* __restrict__ out) {
    extern __shared__ float s[];                 // TILE_FLOATS
    __shared__ __align__(8) uint64_t mbar_s;

    const int tid = threadIdx.x;
    const uint32_t s_base = (uint32_t)__cvta_generic_to_shared(s);
    const uint32_t mb = (uint32_t)__cvta_generic_to_shared(&mbar_s);
    const long long t = blockIdx.x;

    // ---- Issue the tile DMA as early as possible ----
    if (tid == 0) {
        mbar_init(mb, 1);
        asm volatile("fence.proxy.async.shared::cta;" ::: "memory");
        mbar_expect_tx(mb, TILE_BYTES);
        bulk_copy(s_base, in + t * TILE_FLOATS, TILE_BYTES, mb);
    }
    __syncthreads();          // mbar visible to all before waiting
    mbar_wait(mb, 0);

    // ---- Compute: one row per thread (stride 49 -> conflict-free) ----
    const float* row = s + tid * ROW_LEN;

    float t0 = row[0], t1 = row[1], t2 = row[2], t3 = row[3];
    sort4(t0, t1, t2, t3);

    #pragma unroll
    for (int k = 1; k < 12; k++) {
        float c0 = row[4 * k + 0];
        float c1 = row[4 * k + 1];
        float c2 = row[4 * k + 2];
        float c3 = row[4 * k + 3];
        sort4(c0, c1, c2, c3);
        merge4(t0, t1, t2, t3, c0, c1, c2, c3);
    }
    float e = row[48];
    t3 = fmaxf(t3, e);
    ce(t2, t3); ce(t1, t2); ce(t0, t1);

    out[t * TILE_ROWS + tid] = (t0 + t1 + t2 + t3) * 0.25f;
}

extern "C" void kernel_launch(void* const* d_in, const int* in_sizes, int n_in,
                              void* d_out, int out_size) {
    const float* in = (const float*)d_in[0];
    float* out = (float*)d_out;

    const int rows = out_size;                 // 1,048,576
    const int blocks = rows / TILE_ROWS;       // 4096, divides exactly
    const int smem = TILE_BYTES;               // 50,176 B -> 4 CTAs/SM

    cudaFuncSetAttribute(apool_topk4_kernel,
                         cudaFuncAttributeMaxDynamicSharedMemorySize, smem);
    apool_topk4_kernel<<<blocks, THREADS, smem>>>(in, out);
}